// round 4
// baseline (speedup 1.0000x reference)
#include <cuda_runtime.h>

// Fused 2-layer LSTM + dense. B=2048, T=128, D=H1=128, H2=64, OUT=64.
// One CTA per 16 batch rows carries (h,c) through the whole recurrence.
// f32x2 lanes = 2 adjacent gate columns (weights pair-packed k-major, no dup);
// activations (x, h1, h2) stored DUPLICATED in smem so (v,v) ulls load directly.

#define B_TOT 2048
#define T_LEN 128
#define D_IN  128
#define H1    128
#define H2    64
#define OUTD  64
#define NB    16
#define NTH   256
#define ST2   36   // dup'd activation row stride (floats): 32 data + 4 pad, 16B-aligned
#define GSTR  20   // gate staging row stride (floats): 16 data + 4 pad

typedef unsigned long long ull;

// k-major transposed weights (no duplication): WT[k][g] = W[g][k]
__device__ float WT1I[128 * 512];
__device__ float WT1H[128 * 512];
__device__ float WT2I[128 * 256];
__device__ float WT2H[64 * 256];

__device__ __forceinline__ void fma2(ull &d, ull a, ull b) {
    asm("fma.rn.f32x2 %0, %1, %2, %0;" : "+l"(d) : "l"(a), "l"(b));
}
__device__ __forceinline__ ull pack2(float lo, float hi) {
    return (ull)__float_as_uint(lo) | ((ull)__float_as_uint(hi) << 32);
}
__device__ __forceinline__ float lo2(ull v) { return __uint_as_float((unsigned)v); }
__device__ __forceinline__ float hi2(ull v) { return __uint_as_float((unsigned)(v >> 32)); }

__device__ __forceinline__ float sigm(float v) {
    return __fdividef(1.0f, 1.0f + __expf(-v));
}
__device__ __forceinline__ float tanh_(float v) {
    return 2.0f * sigm(2.0f * v) - 1.0f;
}

// ---------------- weight transpose kernel ----------------
__global__ void transpose_kernel(const float* __restrict__ w_ih1,
                                 const float* __restrict__ w_hh1,
                                 const float* __restrict__ w_ih2,
                                 const float* __restrict__ w_hh2) {
    int idx = blockIdx.x * blockDim.x + threadIdx.x;
    if (idx < 65536) {                       // w_ih1: (512,128)
        int g = idx >> 7, k = idx & 127;
        WT1I[k * 512 + g] = w_ih1[idx];
    } else if (idx < 131072) {               // w_hh1: (512,128)
        int i = idx - 65536; int g = i >> 7, k = i & 127;
        WT1H[k * 512 + g] = w_hh1[i];
    } else if (idx < 163840) {               // w_ih2: (256,128)
        int i = idx - 131072; int g = i >> 7, k = i & 127;
        WT2I[k * 256 + g] = w_ih2[i];
    } else if (idx < 180224) {               // w_hh2: (256,64)
        int i = idx - 163840; int g = i >> 6, k = i & 63;
        WT2H[k * 256 + g] = w_hh2[i];
    }
}

// One k-row: 16 dup'd row-ulls from smem, one pair-packed weight ull.
__device__ __forceinline__ void mmrow(ull (&acc)[16], ull w, const float* __restrict__ xr) {
    ulonglong2 a = *(const ulonglong2*)(xr + 0);
    ulonglong2 b = *(const ulonglong2*)(xr + 4);
    ulonglong2 c = *(const ulonglong2*)(xr + 8);
    ulonglong2 d = *(const ulonglong2*)(xr + 12);
    ulonglong2 e = *(const ulonglong2*)(xr + 16);
    ulonglong2 f = *(const ulonglong2*)(xr + 20);
    ulonglong2 g = *(const ulonglong2*)(xr + 24);
    ulonglong2 h = *(const ulonglong2*)(xr + 28);
    fma2(acc[0],  a.x, w); fma2(acc[1],  a.y, w);
    fma2(acc[2],  b.x, w); fma2(acc[3],  b.y, w);
    fma2(acc[4],  c.x, w); fma2(acc[5],  c.y, w);
    fma2(acc[6],  d.x, w); fma2(acc[7],  d.y, w);
    fma2(acc[8],  e.x, w); fma2(acc[9],  e.y, w);
    fma2(acc[10], f.x, w); fma2(acc[11], f.y, w);
    fma2(acc[12], g.x, w); fma2(acc[13], g.y, w);
    fma2(acc[14], h.x, w); fma2(acc[15], h.y, w);
}

// Accumulate over K k-rows starting at k0. WSTR = ulls per weight row.
// wq already offset by this thread's gate-pair index.
template<int WSTR, int K>
__device__ __forceinline__ void mmacc(ull (&acc)[16], const ull* __restrict__ wq,
                                      const float* __restrict__ xb, int k0) {
    const ull* w = wq + k0 * WSTR;
    const float* xbase = xb + k0 * ST2;
    ull wb0[4], wb1[4];
#pragma unroll
    for (int u = 0; u < 4; u++) wb0[u] = w[u * WSTR];
#pragma unroll
    for (int u = 0; u < 4; u++) wb1[u] = w[(4 + u) * WSTR];
#pragma unroll 1
    for (int kb = 0; kb < K; kb += 8) {
#pragma unroll
        for (int u = 0; u < 4; u++) mmrow(acc, wb0[u], xbase + (kb + u) * ST2);
        if (kb + 8 < K) {
#pragma unroll
            for (int u = 0; u < 4; u++) wb0[u] = w[(kb + 8 + u) * WSTR];
        }
#pragma unroll
        for (int u = 0; u < 4; u++) mmrow(acc, wb1[u], xbase + (kb + 4 + u) * ST2);
        if (kb + 12 < K) {
#pragma unroll
            for (int u = 0; u < 4; u++) wb1[u] = w[(kb + 12 + u) * WSTR];
        }
    }
}

// ---------------- main fused kernel ----------------
__global__ void __launch_bounds__(NTH, 1)
lstm_main(const float* __restrict__ x,
          const float* __restrict__ b_ih1, const float* __restrict__ b_hh1,
          const float* __restrict__ b_ih2, const float* __restrict__ b_hh2,
          const float* __restrict__ w_dense, const float* __restrict__ b_dense,
          float* __restrict__ out) {
    extern __shared__ float sm[];
    float* xbuf  = sm;                    // [128][ST2] x_t  duplicated
    float* h1buf = xbuf  + 128 * ST2;     // [128][ST2] h1   duplicated
    float* h2buf = h1buf + 128 * ST2;     // [64][ST2]  h2   duplicated
    float* gbuf  = h2buf + 64 * ST2;      // [512][GSTR] gate staging

    const int t  = threadIdx.x;
    const int b0 = blockIdx.x * NB;

    for (int i = t; i < (128 + 128 + 64) * ST2 + 512 * GSTR; i += NTH) sm[i] = 0.0f;

    // ---- biases (lanes = gate pair) ----
    ull bias1 = pack2(b_ih1[2 * t]     + b_hh1[2 * t],
                      b_ih1[2 * t + 1] + b_hh1[2 * t + 1]);
    const int p = t & 127;                // layer2 gate pair index
    const int halfB = t >> 7;             // 0: k-lower half, 1: k-upper half
    ull bias2 = halfB ? 0ull
                      : pack2(b_ih2[2 * p]     + b_hh2[2 * p],
                              b_ih2[2 * p + 1] + b_hh2[2 * p + 1]);
    const int kih0 = halfB * 64;
    const int khh0 = halfB * 32;

    // elementwise role constants
    const int j1  = t & 127;              // layer1 unit
    const int r0h = (t >> 7) * 8;         // 8 rows
    const int j2  = t & 63;               // layer2 unit
    const int r0q = (t >> 6) * 4;         // 4 rows

    float c1s[8], c2s[4];
#pragma unroll
    for (int i = 0; i < 8; i++) c1s[i] = 0.0f;
#pragma unroll
    for (int i = 0; i < 4; i++) c2s[i] = 0.0f;

    const ull* wq1i = (const ull*)WT1I + t;   // gate pair (2t, 2t+1)
    const ull* wq1h = (const ull*)WT1H + t;
    const ull* wq2i = (const ull*)WT2I + p;   // gate pair (2p, 2p+1)
    const ull* wq2h = (const ull*)WT2H + p;

    const int xr_row = t >> 4;            // 0..15
    const int xr_d0  = (t & 15) * 8;      // 0..120

    __syncthreads();

#pragma unroll 1
    for (int step = 0; step < T_LEN; ++step) {
        // ---- stage x_t transposed + duplicated into xbuf[d][2r],[2r+1] ----
        {
            const float* xr = x + ((b0 + xr_row) * T_LEN + step) * D_IN + xr_d0;
            float4 u0 = *(const float4*)xr;
            float4 u1 = *(const float4*)(xr + 4);
            float v[8] = {u0.x, u0.y, u0.z, u0.w, u1.x, u1.y, u1.z, u1.w};
#pragma unroll
            for (int j = 0; j < 8; j++)
                *(float2*)&xbuf[(xr_d0 + j) * ST2 + 2 * xr_row] = make_float2(v[j], v[j]);
        }
        __syncthreads();   // S1: xbuf ready; prev-step h2buf/gbuf reads done

        // ---- layer1 gates: acc = bias + x·Wih1^T + h1·Whh1^T ----
        {
            ull acc[16];
#pragma unroll
            for (int r = 0; r < 16; r++) acc[r] = bias1;
            mmacc<256, 128>(acc, wq1i, xbuf, 0);
            mmacc<256, 128>(acc, wq1h, h1buf, 0);
            float* gc0 = gbuf + (2 * t) * GSTR;
            float* gc1 = gc0 + GSTR;
#pragma unroll
            for (int j = 0; j < 4; j++) {
                *(float4*)(gc0 + 4 * j) = make_float4(lo2(acc[4*j]), lo2(acc[4*j+1]),
                                                      lo2(acc[4*j+2]), lo2(acc[4*j+3]));
                *(float4*)(gc1 + 4 * j) = make_float4(hi2(acc[4*j]), hi2(acc[4*j+1]),
                                                      hi2(acc[4*j+2]), hi2(acc[4*j+3]));
            }
        }
        __syncthreads();   // S2: gbuf(L1) complete; xbuf/h1buf reads done

        // ---- layer1 elementwise: unit j1, rows r0h..r0h+7 ----
        {
            float gi[8], gf[8], gg[8], go[8];
            float4 a, b;
            a = *(const float4*)&gbuf[(j1) * GSTR + r0h];
            b = *(const float4*)&gbuf[(j1) * GSTR + r0h + 4];
            gi[0]=a.x; gi[1]=a.y; gi[2]=a.z; gi[3]=a.w; gi[4]=b.x; gi[5]=b.y; gi[6]=b.z; gi[7]=b.w;
            a = *(const float4*)&gbuf[(128 + j1) * GSTR + r0h];
            b = *(const float4*)&gbuf[(128 + j1) * GSTR + r0h + 4];
            gf[0]=a.x; gf[1]=a.y; gf[2]=a.z; gf[3]=a.w; gf[4]=b.x; gf[5]=b.y; gf[6]=b.z; gf[7]=b.w;
            a = *(const float4*)&gbuf[(256 + j1) * GSTR + r0h];
            b = *(const float4*)&gbuf[(256 + j1) * GSTR + r0h + 4];
            gg[0]=a.x; gg[1]=a.y; gg[2]=a.z; gg[3]=a.w; gg[4]=b.x; gg[5]=b.y; gg[6]=b.z; gg[7]=b.w;
            a = *(const float4*)&gbuf[(384 + j1) * GSTR + r0h];
            b = *(const float4*)&gbuf[(384 + j1) * GSTR + r0h + 4];
            go[0]=a.x; go[1]=a.y; go[2]=a.z; go[3]=a.w; go[4]=b.x; go[5]=b.y; go[6]=b.z; go[7]=b.w;
#pragma unroll
            for (int rr = 0; rr < 8; rr++) {
                float iv = sigm(gi[rr]);
                float fv = sigm(gf[rr]);
                float gv = tanh_(gg[rr]);
                float ov = sigm(go[rr]);
                c1s[rr] = fv * c1s[rr] + iv * gv;
                float hv = ov * tanh_(c1s[rr]);
                *(float2*)&h1buf[j1 * ST2 + 2 * (r0h + rr)] = make_float2(hv, hv);
            }
        }
        __syncthreads();   // S3: h1buf ready; gbuf(L1) reads done

        // ---- layer2 gates, split-K across thread halves ----
        {
            ull acc2[16];
#pragma unroll
            for (int r = 0; r < 16; r++) acc2[r] = bias2;
            mmacc<128, 64>(acc2, wq2i, h1buf, kih0);
            mmacc<128, 32>(acc2, wq2h, h2buf, khh0);
            // partial A -> cols [0,256), partial B -> cols [256,512)
            float* gc0 = gbuf + (halfB * 256 + 2 * p) * GSTR;
            float* gc1 = gc0 + GSTR;
#pragma unroll
            for (int j = 0; j < 4; j++) {
                *(float4*)(gc0 + 4 * j) = make_float4(lo2(acc2[4*j]), lo2(acc2[4*j+1]),
                                                      lo2(acc2[4*j+2]), lo2(acc2[4*j+3]));
                *(float4*)(gc1 + 4 * j) = make_float4(hi2(acc2[4*j]), hi2(acc2[4*j+1]),
                                                      hi2(acc2[4*j+2]), hi2(acc2[4*j+3]));
            }
        }
        __syncthreads();   // S4: both partials staged; h1buf/h2buf reads done

        // ---- layer2 elementwise: unit j2, rows r0q..r0q+3 (sum two partials) ----
        {
            float4 giA = *(const float4*)&gbuf[(j2) * GSTR + r0q];
            float4 giB = *(const float4*)&gbuf[(256 + j2) * GSTR + r0q];
            float4 gfA = *(const float4*)&gbuf[(64 + j2) * GSTR + r0q];
            float4 gfB = *(const float4*)&gbuf[(320 + j2) * GSTR + r0q];
            float4 ggA = *(const float4*)&gbuf[(128 + j2) * GSTR + r0q];
            float4 ggB = *(const float4*)&gbuf[(384 + j2) * GSTR + r0q];
            float4 goA = *(const float4*)&gbuf[(192 + j2) * GSTR + r0q];
            float4 goB = *(const float4*)&gbuf[(448 + j2) * GSTR + r0q];
            float gia[4] = {giA.x + giB.x, giA.y + giB.y, giA.z + giB.z, giA.w + giB.w};
            float gfa[4] = {gfA.x + gfB.x, gfA.y + gfB.y, gfA.z + gfB.z, gfA.w + gfB.w};
            float gga[4] = {ggA.x + ggB.x, ggA.y + ggB.y, ggA.z + ggB.z, ggA.w + ggB.w};
            float goa[4] = {goA.x + goB.x, goA.y + goB.y, goA.z + goB.z, goA.w + goB.w};
#pragma unroll
            for (int rr = 0; rr < 4; rr++) {
                float iv = sigm(gia[rr]);
                float fv = sigm(gfa[rr]);
                float gv = tanh_(gga[rr]);
                float ov = sigm(goa[rr]);
                c2s[rr] = fv * c2s[rr] + iv * gv;
                float hv = ov * tanh_(c2s[rr]);
                *(float2*)&h2buf[j2 * ST2 + 2 * (r0q + rr)] = make_float2(hv, hv);
            }
        }
        __syncthreads();   // S5: h2buf ready + gbuf(L2) reads done before next write
    }

    // ---- dense + relu on final h2 (h2buf is duplicated: row r at offset 2r) ----
    {
        int o = t & 63;
        int r0 = (t >> 6) * 4;
        float bd = b_dense[o];
        float a0 = bd, a1 = bd, a2 = bd, a3 = bd;
        const float* wd = w_dense + o * 64;
#pragma unroll 8
        for (int k = 0; k < 64; k++) {
            float wv = wd[k];
            const float* h = &h2buf[k * ST2 + 2 * r0];
            a0 += wv * h[0];
            a1 += wv * h[2];
            a2 += wv * h[4];
            a3 += wv * h[6];
        }
        out[(b0 + r0 + 0) * OUTD + o] = fmaxf(a0, 0.0f);
        out[(b0 + r0 + 1) * OUTD + o] = fmaxf(a1, 0.0f);
        out[(b0 + r0 + 2) * OUTD + o] = fmaxf(a2, 0.0f);
        out[(b0 + r0 + 3) * OUTD + o] = fmaxf(a3, 0.0f);
    }
}

#define SMEM_BYTES (((128 + 128 + 64) * ST2 + 512 * GSTR) * 4)

extern "C" void kernel_launch(void* const* d_in, const int* in_sizes, int n_in,
                              void* d_out, int out_size) {
    const float* x       = (const float*)d_in[0];
    const float* w_ih1   = (const float*)d_in[1];
    const float* w_hh1   = (const float*)d_in[2];
    const float* b_ih1   = (const float*)d_in[3];
    const float* b_hh1   = (const float*)d_in[4];
    const float* w_ih2   = (const float*)d_in[5];
    const float* w_hh2   = (const float*)d_in[6];
    const float* b_ih2   = (const float*)d_in[7];
    const float* b_hh2   = (const float*)d_in[8];
    const float* w_dense = (const float*)d_in[9];
    const float* b_dense = (const float*)d_in[10];
    float* out = (float*)d_out;

    static int attr_set = 0;
    if (!attr_set) {
        cudaFuncSetAttribute(lstm_main, cudaFuncAttributeMaxDynamicSharedMemorySize, SMEM_BYTES);
        attr_set = 1;
    }

    transpose_kernel<<<704, 256>>>(w_ih1, w_hh1, w_ih2, w_hh2);
    lstm_main<<<B_TOT / NB, NTH, SMEM_BYTES>>>(x, b_ih1, b_hh1, b_ih2, b_hh2,
                                               w_dense, b_dense, out);
}

// round 8
// speedup vs baseline: 1.0952x; 1.0952x over previous
#include <cuda_runtime.h>

// Fused 2-layer LSTM + dense. B=2048, T=128, D=H1=128, H2=64, OUT=64.
// One CTA per 16 batch rows carries (h,c) through the whole recurrence.
// P=2 f32x2 column-pairs per thread (4 gate cols), 8 rows (rowsplit=2):
// halves LDS wavefronts per FFMA2 vs the R3 kernel (was the binding pipe).

#define B_TOT 2048
#define T_LEN 128
#define D_IN  128
#define H1    128
#define H2    64
#define OUTD  64
#define NB    16
#define NTH   256
#define ST2   36   // dup'd activation row stride (floats): 32 data + 4 pad
#define GSTR  20   // gate staging row stride (floats): 16 data + 4 pad

typedef unsigned long long ull;

// k-major transposed weights: WT[k][g] = W[g][k]
__device__ float WT1I[128 * 512];
__device__ float WT1H[128 * 512];
__device__ float WT2I[128 * 256];
__device__ float WT2H[64 * 256];

__device__ __forceinline__ void fma2(ull &d, ull a, ull b) {
    asm("fma.rn.f32x2 %0, %1, %2, %0;" : "+l"(d) : "l"(a), "l"(b));
}
__device__ __forceinline__ ull pack2(float lo, float hi) {
    return (ull)__float_as_uint(lo) | ((ull)__float_as_uint(hi) << 32);
}
__device__ __forceinline__ float lo2(ull v) { return __uint_as_float((unsigned)v); }
__device__ __forceinline__ float hi2(ull v) { return __uint_as_float((unsigned)(v >> 32)); }

__device__ __forceinline__ float sigm(float v) {
    return __fdividef(1.0f, 1.0f + __expf(-v));
}
__device__ __forceinline__ float tanh_(float v) {
    return 2.0f * sigm(2.0f * v) - 1.0f;
}

// ---------------- weight transpose kernel ----------------
__global__ void transpose_kernel(const float* __restrict__ w_ih1,
                                 const float* __restrict__ w_hh1,
                                 const float* __restrict__ w_ih2,
                                 const float* __restrict__ w_hh2) {
    int idx = blockIdx.x * blockDim.x + threadIdx.x;
    if (idx < 65536) {                       // w_ih1: (512,128)
        int g = idx >> 7, k = idx & 127;
        WT1I[k * 512 + g] = w_ih1[idx];
    } else if (idx < 131072) {               // w_hh1: (512,128)
        int i = idx - 65536; int g = i >> 7, k = i & 127;
        WT1H[k * 512 + g] = w_hh1[i];
    } else if (idx < 163840) {               // w_ih2: (256,128)
        int i = idx - 131072; int g = i >> 7, k = i & 127;
        WT2I[k * 256 + g] = w_ih2[i];
    } else if (idx < 180224) {               // w_hh2: (256,64)
        int i = idx - 163840; int g = i >> 6, k = i & 63;
        WT2H[k * 256 + g] = w_hh2[i];
    }
}

// One k-row: 8 dup'd rows (4 LDS.128), 2 weight pairs (w.x = cols 4q..4q+1,
// w.y = cols 4q+2..4q+3). 16 FFMA2.
__device__ __forceinline__ void mmrow2(ull (&a0)[8], ull (&a1)[8],
                                       ulonglong2 w, const float* __restrict__ xr) {
    ulonglong2 a = *(const ulonglong2*)(xr + 0);    // rows 0,1 (dup'd)
    ulonglong2 b = *(const ulonglong2*)(xr + 4);    // rows 2,3
    ulonglong2 c = *(const ulonglong2*)(xr + 8);    // rows 4,5
    ulonglong2 d = *(const ulonglong2*)(xr + 12);   // rows 6,7
    fma2(a0[0], a.x, w.x); fma2(a1[0], a.x, w.y);
    fma2(a0[1], a.y, w.x); fma2(a1[1], a.y, w.y);
    fma2(a0[2], b.x, w.x); fma2(a1[2], b.x, w.y);
    fma2(a0[3], b.y, w.x); fma2(a1[3], b.y, w.y);
    fma2(a0[4], c.x, w.x); fma2(a1[4], c.x, w.y);
    fma2(a0[5], c.y, w.x); fma2(a1[5], c.y, w.y);
    fma2(a0[6], d.x, w.x); fma2(a1[6], d.x, w.y);
    fma2(a0[7], d.y, w.x); fma2(a1[7], d.y, w.y);
}

// Accumulate K k-rows. WSTR = ulonglong2 per weight row. wq pre-offset by the
// thread's 16B column chunk. xb pre-offset by the thread's row-half.
template<int WSTR, int K>
__device__ __forceinline__ void mmacc(ull (&a0)[8], ull (&a1)[8],
                                      const ulonglong2* __restrict__ wq,
                                      const float* __restrict__ xb, int k0) {
    const ulonglong2* w = wq + k0 * WSTR;
    const float* xbase = xb + k0 * ST2;
    ulonglong2 wb0[4], wb1[4];
#pragma unroll
    for (int u = 0; u < 4; u++) wb0[u] = w[u * WSTR];
#pragma unroll
    for (int u = 0; u < 4; u++) wb1[u] = w[(4 + u) * WSTR];
#pragma unroll 1
    for (int kb = 0; kb < K; kb += 8) {
#pragma unroll
        for (int u = 0; u < 4; u++) mmrow2(a0, a1, wb0[u], xbase + (kb + u) * ST2);
        if (kb + 8 < K) {
#pragma unroll
            for (int u = 0; u < 4; u++) wb0[u] = w[(kb + 8 + u) * WSTR];
        }
#pragma unroll
        for (int u = 0; u < 4; u++) mmrow2(a0, a1, wb1[u], xbase + (kb + 4 + u) * ST2);
        if (kb + 12 < K) {
#pragma unroll
            for (int u = 0; u < 4; u++) wb1[u] = w[(kb + 12 + u) * WSTR];
        }
    }
}

// stage: acc lane-split into 4 cols x 8 rows of gbuf
__device__ __forceinline__ void stage4(float* gc, ull (&a0)[8], ull (&a1)[8]) {
    *(float4*)(gc + 0 * GSTR)     = make_float4(lo2(a0[0]), lo2(a0[1]), lo2(a0[2]), lo2(a0[3]));
    *(float4*)(gc + 0 * GSTR + 4) = make_float4(lo2(a0[4]), lo2(a0[5]), lo2(a0[6]), lo2(a0[7]));
    *(float4*)(gc + 1 * GSTR)     = make_float4(hi2(a0[0]), hi2(a0[1]), hi2(a0[2]), hi2(a0[3]));
    *(float4*)(gc + 1 * GSTR + 4) = make_float4(hi2(a0[4]), hi2(a0[5]), hi2(a0[6]), hi2(a0[7]));
    *(float4*)(gc + 2 * GSTR)     = make_float4(lo2(a1[0]), lo2(a1[1]), lo2(a1[2]), lo2(a1[3]));
    *(float4*)(gc + 2 * GSTR + 4) = make_float4(lo2(a1[4]), lo2(a1[5]), lo2(a1[6]), lo2(a1[7]));
    *(float4*)(gc + 3 * GSTR)     = make_float4(hi2(a1[0]), hi2(a1[1]), hi2(a1[2]), hi2(a1[3]));
    *(float4*)(gc + 3 * GSTR + 4) = make_float4(hi2(a1[4]), hi2(a1[5]), hi2(a1[6]), hi2(a1[7]));
}

// ---------------- main fused kernel ----------------
__global__ void __launch_bounds__(NTH, 1)
lstm_main(const float* __restrict__ x,
          const float* __restrict__ b_ih1, const float* __restrict__ b_hh1,
          const float* __restrict__ b_ih2, const float* __restrict__ b_hh2,
          const float* __restrict__ w_dense, const float* __restrict__ b_dense,
          float* __restrict__ out) {
    extern __shared__ float sm[];
    float* xbuf  = sm;                    // [128][ST2] x_t  duplicated
    float* h1buf = xbuf  + 128 * ST2;     // [128][ST2] h1   duplicated
    float* h2buf = h1buf + 128 * ST2;     // [64][ST2]  h2   duplicated
    float* gbuf  = h2buf + 64 * ST2;      // [512][GSTR] gate staging

    const int t  = threadIdx.x;
    const int b0 = blockIdx.x * NB;

    for (int i = t; i < (128 + 128 + 64) * ST2 + 512 * GSTR; i += NTH) sm[i] = 0.0f;

    // ---- layer1 matmul role: q1 in [0,128) -> cols 4q1..4q1+3; rh1 row-half ----
    const int q1  = t & 127;
    const int rh1 = t >> 7;               // 0/1 -> rows 8*rh1..8*rh1+7
    ull b1a = pack2(b_ih1[4 * q1]     + b_hh1[4 * q1],
                    b_ih1[4 * q1 + 1] + b_hh1[4 * q1 + 1]);
    ull b1b = pack2(b_ih1[4 * q1 + 2] + b_hh1[4 * q1 + 2],
                    b_ih1[4 * q1 + 3] + b_hh1[4 * q1 + 3]);

    // ---- layer2 matmul role: q2 in [0,64), rh2 row-half, kh k-half ----
    const int q2  = t & 63;
    const int rh2 = (t >> 6) & 1;
    const int kh  = t >> 7;
    ull b2a = kh ? 0ull : pack2(b_ih2[4 * q2]     + b_hh2[4 * q2],
                                b_ih2[4 * q2 + 1] + b_hh2[4 * q2 + 1]);
    ull b2b = kh ? 0ull : pack2(b_ih2[4 * q2 + 2] + b_hh2[4 * q2 + 2],
                                b_ih2[4 * q2 + 3] + b_hh2[4 * q2 + 3]);
    const int kih0 = kh * 64;
    const int khh0 = kh * 32;

    // elementwise role constants
    const int j1  = t & 127;              // layer1 unit
    const int r0h = (t >> 7) * 8;         // 8 rows
    const int j2  = t & 63;               // layer2 unit
    const int r0q = (t >> 6) * 4;         // 4 rows

    float c1s[8], c2s[4];
#pragma unroll
    for (int i = 0; i < 8; i++) c1s[i] = 0.0f;
#pragma unroll
    for (int i = 0; i < 4; i++) c2s[i] = 0.0f;

    const ulonglong2* wq1i = (const ulonglong2*)WT1I + q1;   // row stride 128 u2
    const ulonglong2* wq1h = (const ulonglong2*)WT1H + q1;
    const ulonglong2* wq2i = (const ulonglong2*)WT2I + q2;   // row stride 64 u2
    const ulonglong2* wq2h = (const ulonglong2*)WT2H + q2;

    const int xr_row = t >> 4;            // 0..15
    const int xr_d0  = (t & 15) * 8;      // 0..120

    __syncthreads();

#pragma unroll 1
    for (int step = 0; step < T_LEN; ++step) {
        // ---- stage x_t transposed + duplicated into xbuf[d][2r],[2r+1] ----
        {
            const float* xr = x + ((b0 + xr_row) * T_LEN + step) * D_IN + xr_d0;
            float4 u0 = *(const float4*)xr;
            float4 u1 = *(const float4*)(xr + 4);
            float v[8] = {u0.x, u0.y, u0.z, u0.w, u1.x, u1.y, u1.z, u1.w};
#pragma unroll
            for (int j = 0; j < 8; j++)
                *(float2*)&xbuf[(xr_d0 + j) * ST2 + 2 * xr_row] = make_float2(v[j], v[j]);
        }
        __syncthreads();   // S1: xbuf ready; prev-step gbuf/h2buf reads complete

        // ---- layer1 gates: bias + x·Wih1^T + h1·Whh1^T ----
        {
            ull a0[8], a1[8];
#pragma unroll
            for (int r = 0; r < 8; r++) { a0[r] = b1a; a1[r] = b1b; }
            mmacc<128, 128>(a0, a1, wq1i, xbuf  + 16 * rh1, 0);
            mmacc<128, 128>(a0, a1, wq1h, h1buf + 16 * rh1, 0);
            stage4(gbuf + (4 * q1) * GSTR + 8 * rh1, a0, a1);
        }
        __syncthreads();   // S2: gbuf(L1) complete; xbuf/h1buf reads done

        // ---- layer1 elementwise: unit j1, rows r0h..r0h+7 ----
        {
            float gi[8], gf[8], gg[8], go[8];
            float4 a, b;
            a = *(const float4*)&gbuf[(j1) * GSTR + r0h];
            b = *(const float4*)&gbuf[(j1) * GSTR + r0h + 4];
            gi[0]=a.x; gi[1]=a.y; gi[2]=a.z; gi[3]=a.w; gi[4]=b.x; gi[5]=b.y; gi[6]=b.z; gi[7]=b.w;
            a = *(const float4*)&gbuf[(128 + j1) * GSTR + r0h];
            b = *(const float4*)&gbuf[(128 + j1) * GSTR + r0h + 4];
            gf[0]=a.x; gf[1]=a.y; gf[2]=a.z; gf[3]=a.w; gf[4]=b.x; gf[5]=b.y; gf[6]=b.z; gf[7]=b.w;
            a = *(const float4*)&gbuf[(256 + j1) * GSTR + r0h];
            b = *(const float4*)&gbuf[(256 + j1) * GSTR + r0h + 4];
            gg[0]=a.x; gg[1]=a.y; gg[2]=a.z; gg[3]=a.w; gg[4]=b.x; gg[5]=b.y; gg[6]=b.z; gg[7]=b.w;
            a = *(const float4*)&gbuf[(384 + j1) * GSTR + r0h];
            b = *(const float4*)&gbuf[(384 + j1) * GSTR + r0h + 4];
            go[0]=a.x; go[1]=a.y; go[2]=a.z; go[3]=a.w; go[4]=b.x; go[5]=b.y; go[6]=b.z; go[7]=b.w;
#pragma unroll
            for (int rr = 0; rr < 8; rr++) {
                float iv = sigm(gi[rr]);
                float fv = sigm(gf[rr]);
                float gv = tanh_(gg[rr]);
                float ov = sigm(go[rr]);
                c1s[rr] = fv * c1s[rr] + iv * gv;
                float hv = ov * tanh_(c1s[rr]);
                *(float2*)&h1buf[j1 * ST2 + 2 * (r0h + rr)] = make_float2(hv, hv);
            }
        }
        __syncthreads();   // S3: h1buf ready; gbuf(L1) reads done

        // ---- layer2 gates, split-K across thread halves ----
        {
            ull a0[8], a1[8];
#pragma unroll
            for (int r = 0; r < 8; r++) { a0[r] = b2a; a1[r] = b2b; }
            mmacc<64, 64>(a0, a1, wq2i, h1buf + 16 * rh2, kih0);
            mmacc<64, 32>(a0, a1, wq2h, h2buf + 16 * rh2, khh0);
            stage4(gbuf + (kh * 256 + 4 * q2) * GSTR + 8 * rh2, a0, a1);
        }
        __syncthreads();   // S4: both partials staged; h1buf/h2buf reads done

        // ---- layer2 elementwise: unit j2, rows r0q..r0q+3 (sum partials) ----
        {
            float4 giA = *(const float4*)&gbuf[(j2) * GSTR + r0q];
            float4 giB = *(const float4*)&gbuf[(256 + j2) * GSTR + r0q];
            float4 gfA = *(const float4*)&gbuf[(64 + j2) * GSTR + r0q];
            float4 gfB = *(const float4*)&gbuf[(320 + j2) * GSTR + r0q];
            float4 ggA = *(const float4*)&gbuf[(128 + j2) * GSTR + r0q];
            float4 ggB = *(const float4*)&gbuf[(384 + j2) * GSTR + r0q];
            float4 goA = *(const float4*)&gbuf[(192 + j2) * GSTR + r0q];
            float4 goB = *(const float4*)&gbuf[(448 + j2) * GSTR + r0q];
            float gia[4] = {giA.x + giB.x, giA.y + giB.y, giA.z + giB.z, giA.w + giB.w};
            float gfa[4] = {gfA.x + gfB.x, gfA.y + gfB.y, gfA.z + gfB.z, gfA.w + gfB.w};
            float gga[4] = {ggA.x + ggB.x, ggA.y + ggB.y, ggA.z + ggB.z, ggA.w + ggB.w};
            float goa[4] = {goA.x + goB.x, goA.y + goB.y, goA.z + goB.z, goA.w + goB.w};
#pragma unroll
            for (int rr = 0; rr < 4; rr++) {
                float iv = sigm(gia[rr]);
                float fv = sigm(gfa[rr]);
                float gv = tanh_(gga[rr]);
                float ov = sigm(goa[rr]);
                c2s[rr] = fv * c2s[rr] + iv * gv;
                float hv = ov * tanh_(c2s[rr]);
                *(float2*)&h2buf[j2 * ST2 + 2 * (r0q + rr)] = make_float2(hv, hv);
            }
        }
        // no barrier: next-step S1 orders gbuf/h2buf reads vs subsequent writes
    }

    __syncthreads();   // h2buf final values visible to all threads

    // ---- dense + relu on final h2 (duplicated rows: row r at offset 2r) ----
    {
        int o = t & 63;
        int r0 = (t >> 6) * 4;
        float bd = b_dense[o];
        float a0 = bd, a1 = bd, a2 = bd, a3 = bd;
        const float* wd = w_dense + o * 64;
#pragma unroll 8
        for (int k = 0; k < 64; k++) {
            float wv = wd[k];
            const float* h = &h2buf[k * ST2 + 2 * r0];
            a0 += wv * h[0];
            a1 += wv * h[2];
            a2 += wv * h[4];
            a3 += wv * h[6];
        }
        out[(b0 + r0 + 0) * OUTD + o] = fmaxf(a0, 0.0f);
        out[(b0 + r0 + 1) * OUTD + o] = fmaxf(a1, 0.0f);
        out[(b0 + r0 + 2) * OUTD + o] = fmaxf(a2, 0.0f);
        out[(b0 + r0 + 3) * OUTD + o] = fmaxf(a3, 0.0f);
    }
}

#define SMEM_BYTES (((128 + 128 + 64) * ST2 + 512 * GSTR) * 4)

extern "C" void kernel_launch(void* const* d_in, const int* in_sizes, int n_in,
                              void* d_out, int out_size) {
    const float* x       = (const float*)d_in[0];
    const float* w_ih1   = (const float*)d_in[1];
    const float* w_hh1   = (const float*)d_in[2];
    const float* b_ih1   = (const float*)d_in[3];
    const float* b_hh1   = (const float*)d_in[4];
    const float* w_ih2   = (const float*)d_in[5];
    const float* w_hh2   = (const float*)d_in[6];
    const float* b_ih2   = (const float*)d_in[7];
    const float* b_hh2   = (const float*)d_in[8];
    const float* w_dense = (const float*)d_in[9];
    const float* b_dense = (const float*)d_in[10];
    float* out = (float*)d_out;

    static int attr_set = 0;
    if (!attr_set) {
        cudaFuncSetAttribute(lstm_main, cudaFuncAttributeMaxDynamicSharedMemorySize, SMEM_BYTES);
        attr_set = 1;
    }

    transpose_kernel<<<704, 256>>>(w_ih1, w_hh1, w_ih2, w_hh2);
    lstm_main<<<B_TOT / NB, NTH, SMEM_BYTES>>>(x, b_ih1, b_hh1, b_ih2, b_hh2,
                                               w_dense, b_dense, out);
}

// round 9
// speedup vs baseline: 1.2529x; 1.1440x over previous
#include <cuda_runtime.h>

// Fused 2-layer LSTM + dense. B=2048, T=128, D=H1=128, H2=64, OUT=64.
// grid=128 CTAs x 512 threads (16 warps/SM): one CTA per 16 batch rows.
// P=2 f32x2 col-pairs (4 gate cols) x 8 rows per thread; k-split 2 (L1) /
// 4 (L2) across thread groups, partials summed in the elementwise phase.
// gbuf is row-major [16][GROW] so gate staging stores/loads are conflict-free.

#define B_TOT 2048
#define T_LEN 128
#define D_IN  128
#define H1    128
#define H2    64
#define OUTD  64
#define NB    16
#define NTH   512
#define ST2   36     // dup'd activation row stride (floats): 32 data + 4 pad
#define GROW  1040   // gbuf row stride (floats): 1024 cols + 16 pad

typedef unsigned long long ull;

// k-major transposed weights: WT[k][g] = W[g][k]
__device__ float WT1I[128 * 512];
__device__ float WT1H[128 * 512];
__device__ float WT2I[128 * 256];
__device__ float WT2H[64 * 256];

__device__ __forceinline__ void fma2(ull &d, ull a, ull b) {
    asm("fma.rn.f32x2 %0, %1, %2, %0;" : "+l"(d) : "l"(a), "l"(b));
}
__device__ __forceinline__ ull pack2(float lo, float hi) {
    return (ull)__float_as_uint(lo) | ((ull)__float_as_uint(hi) << 32);
}
__device__ __forceinline__ float lo2(ull v) { return __uint_as_float((unsigned)v); }
__device__ __forceinline__ float hi2(ull v) { return __uint_as_float((unsigned)(v >> 32)); }

__device__ __forceinline__ float sigm(float v) {
    return __fdividef(1.0f, 1.0f + __expf(-v));
}
__device__ __forceinline__ float tanh_(float v) {
    return 2.0f * sigm(2.0f * v) - 1.0f;
}

// ---------------- weight transpose kernel ----------------
__global__ void transpose_kernel(const float* __restrict__ w_ih1,
                                 const float* __restrict__ w_hh1,
                                 const float* __restrict__ w_ih2,
                                 const float* __restrict__ w_hh2) {
    int idx = blockIdx.x * blockDim.x + threadIdx.x;
    if (idx < 65536) {                       // w_ih1: (512,128)
        int g = idx >> 7, k = idx & 127;
        WT1I[k * 512 + g] = w_ih1[idx];
    } else if (idx < 131072) {               // w_hh1: (512,128)
        int i = idx - 65536; int g = i >> 7, k = i & 127;
        WT1H[k * 512 + g] = w_hh1[i];
    } else if (idx < 163840) {               // w_ih2: (256,128)
        int i = idx - 131072; int g = i >> 7, k = i & 127;
        WT2I[k * 256 + g] = w_ih2[i];
    } else if (idx < 180224) {               // w_hh2: (256,64)
        int i = idx - 163840; int g = i >> 6, k = i & 63;
        WT2H[k * 256 + g] = w_hh2[i];
    }
}

// One k-row: 8 dup'd rows (4 LDS.128), 2 weight pairs. 16 FFMA2.
__device__ __forceinline__ void mmrow2(ull (&a0)[8], ull (&a1)[8],
                                       ulonglong2 w, const float* __restrict__ xr) {
    ulonglong2 a = *(const ulonglong2*)(xr + 0);    // rows 0,1 (dup'd)
    ulonglong2 b = *(const ulonglong2*)(xr + 4);    // rows 2,3
    ulonglong2 c = *(const ulonglong2*)(xr + 8);    // rows 4,5
    ulonglong2 d = *(const ulonglong2*)(xr + 12);   // rows 6,7
    fma2(a0[0], a.x, w.x); fma2(a1[0], a.x, w.y);
    fma2(a0[1], a.y, w.x); fma2(a1[1], a.y, w.y);
    fma2(a0[2], b.x, w.x); fma2(a1[2], b.x, w.y);
    fma2(a0[3], b.y, w.x); fma2(a1[3], b.y, w.y);
    fma2(a0[4], c.x, w.x); fma2(a1[4], c.x, w.y);
    fma2(a0[5], c.y, w.x); fma2(a1[5], c.y, w.y);
    fma2(a0[6], d.x, w.x); fma2(a1[6], d.x, w.y);
    fma2(a0[7], d.y, w.x); fma2(a1[7], d.y, w.y);
}

// Accumulate K k-rows starting at k0. WSTR = ulonglong2 per weight row.
// wq pre-offset by the thread's 16B column chunk; xb pre-offset by row-half.
template<int WSTR, int K>
__device__ __forceinline__ void mmacc(ull (&a0)[8], ull (&a1)[8],
                                      const ulonglong2* __restrict__ wq,
                                      const float* __restrict__ xb, int k0) {
    const ulonglong2* w = wq + k0 * WSTR;
    const float* xbase = xb + k0 * ST2;
    ulonglong2 wb0[4], wb1[4];
#pragma unroll
    for (int u = 0; u < 4; u++) wb0[u] = w[u * WSTR];
#pragma unroll
    for (int u = 0; u < 4; u++) wb1[u] = w[(4 + u) * WSTR];
#pragma unroll 1
    for (int kb = 0; kb < K; kb += 8) {
#pragma unroll
        for (int u = 0; u < 4; u++) mmrow2(a0, a1, wb0[u], xbase + (kb + u) * ST2);
        if (kb + 8 < K) {
#pragma unroll
            for (int u = 0; u < 4; u++) wb0[u] = w[(kb + 8 + u) * WSTR];
        }
#pragma unroll
        for (int u = 0; u < 4; u++) mmrow2(a0, a1, wb1[u], xbase + (kb + 4 + u) * ST2);
        if (kb + 12 < K) {
#pragma unroll
            for (int u = 0; u < 4; u++) wb1[u] = w[(kb + 12 + u) * WSTR];
        }
    }
}

// stage: 8 rows x 4 cols into row-major gbuf; lane-consecutive float4 stores.
__device__ __forceinline__ void stage8(float* gc, ull (&a0)[8], ull (&a1)[8]) {
#pragma unroll
    for (int r = 0; r < 8; r++)
        *(float4*)(gc + r * GROW) = make_float4(lo2(a0[r]), hi2(a0[r]),
                                                lo2(a1[r]), hi2(a1[r]));
}

// ---------------- main fused kernel ----------------
__global__ void __launch_bounds__(NTH, 1)
lstm_main(const float* __restrict__ x,
          const float* __restrict__ b_ih1, const float* __restrict__ b_hh1,
          const float* __restrict__ b_ih2, const float* __restrict__ b_hh2,
          const float* __restrict__ w_dense, const float* __restrict__ b_dense,
          float* __restrict__ out) {
    extern __shared__ float sm[];
    float* xbuf  = sm;                    // [128][ST2] x_t  duplicated
    float* h1buf = xbuf  + 128 * ST2;     // [128][ST2] h1   duplicated
    float* h2buf = h1buf + 128 * ST2;     // [64][ST2]  h2   duplicated
    float* gbuf  = h2buf + 64 * ST2;      // [16][GROW] gate staging, row-major

    const int t  = threadIdx.x;
    const int b0 = blockIdx.x * NB;

    for (int i = t; i < (128 + 128 + 64) * ST2 + 16 * GROW; i += NTH) sm[i] = 0.0f;

    // ---- layer1 matmul role: cols 4q1..4q1+3, rows 8*rh1.., k-half kh1 ----
    const int q1  = t & 127;
    const int rh1 = (t >> 7) & 1;
    const int kh1 = t >> 8;               // 0/1
    ull b1a = 0, b1b = 0;
    if (kh1 == 0) {
        b1a = pack2(b_ih1[4 * q1]     + b_hh1[4 * q1],
                    b_ih1[4 * q1 + 1] + b_hh1[4 * q1 + 1]);
        b1b = pack2(b_ih1[4 * q1 + 2] + b_hh1[4 * q1 + 2],
                    b_ih1[4 * q1 + 3] + b_hh1[4 * q1 + 3]);
    }

    // ---- layer2 matmul role: cols 4q2.., rows 8*rh2.., k-quarter kq ----
    const int q2  = t & 63;
    const int rh2 = (t >> 6) & 1;
    const int kq  = t >> 7;               // 0..3
    ull b2a = 0, b2b = 0;
    if (kq == 0) {
        b2a = pack2(b_ih2[4 * q2]     + b_hh2[4 * q2],
                    b_ih2[4 * q2 + 1] + b_hh2[4 * q2 + 1]);
        b2b = pack2(b_ih2[4 * q2 + 2] + b_hh2[4 * q2 + 2],
                    b_ih2[4 * q2 + 3] + b_hh2[4 * q2 + 3]);
    }

    // elementwise roles
    const int j1  = t & 127;              // layer1 unit
    const int r0h = (t >> 7) * 4;         // 4 rows
    const int j2  = t & 63;               // layer2 unit
    const int r0q = (t >> 6) * 2;         // 2 rows

    float c1s[4], c2s[2];
#pragma unroll
    for (int i = 0; i < 4; i++) c1s[i] = 0.0f;
    c2s[0] = c2s[1] = 0.0f;

    const ulonglong2* wq1i = (const ulonglong2*)WT1I + q1;   // row stride 128 u2
    const ulonglong2* wq1h = (const ulonglong2*)WT1H + q1;
    const ulonglong2* wq2i = (const ulonglong2*)WT2I + q2;   // row stride 64 u2
    const ulonglong2* wq2h = (const ulonglong2*)WT2H + q2;

    const int xr_row = t >> 5;            // 0..15
    const int xr_d0  = (t & 31) * 4;      // 0..124

    __syncthreads();

#pragma unroll 1
    for (int step = 0; step < T_LEN; ++step) {
        // ---- stage x_t transposed + duplicated into xbuf[d][2r],[2r+1] ----
        {
            const float* xr = x + ((b0 + xr_row) * T_LEN + step) * D_IN + xr_d0;
            float4 u = *(const float4*)xr;
            *(float2*)&xbuf[(xr_d0 + 0) * ST2 + 2 * xr_row] = make_float2(u.x, u.x);
            *(float2*)&xbuf[(xr_d0 + 1) * ST2 + 2 * xr_row] = make_float2(u.y, u.y);
            *(float2*)&xbuf[(xr_d0 + 2) * ST2 + 2 * xr_row] = make_float2(u.z, u.z);
            *(float2*)&xbuf[(xr_d0 + 3) * ST2 + 2 * xr_row] = make_float2(u.w, u.w);
        }
        __syncthreads();   // S1: xbuf ready; prev-step gbuf reads complete

        // ---- layer1 gates (k-half): bias + x·Wih1^T + h1·Whh1^T ----
        {
            ull a0[8], a1[8];
#pragma unroll
            for (int r = 0; r < 8; r++) { a0[r] = b1a; a1[r] = b1b; }
            mmacc<128, 64>(a0, a1, wq1i, xbuf  + 16 * rh1, kh1 * 64);
            mmacc<128, 64>(a0, a1, wq1h, h1buf + 16 * rh1, kh1 * 64);
            stage8(gbuf + (8 * rh1) * GROW + kh1 * 512 + 4 * q1, a0, a1);
        }
        __syncthreads();   // S2: gbuf(L1) complete; xbuf/h1buf reads done

        // ---- layer1 elementwise: unit j1, rows r0h..r0h+3 (sum 2 partials) ----
        {
#pragma unroll
            for (int r = 0; r < 4; r++) {
                int row = r0h + r;
                const float* gr = gbuf + row * GROW;
                float gi = gr[j1]       + gr[512 + j1];
                float gf = gr[128 + j1] + gr[640 + j1];
                float gg = gr[256 + j1] + gr[768 + j1];
                float go = gr[384 + j1] + gr[896 + j1];
                float iv = sigm(gi);
                float fv = sigm(gf);
                float gv = tanh_(gg);
                float ov = sigm(go);
                c1s[r] = fv * c1s[r] + iv * gv;
                float hv = ov * tanh_(c1s[r]);
                *(float2*)&h1buf[j1 * ST2 + 2 * row] = make_float2(hv, hv);
            }
        }
        __syncthreads();   // S3: h1buf ready; gbuf(L1) reads done

        // ---- layer2 gates (k-quarter) ----
        {
            ull a0[8], a1[8];
#pragma unroll
            for (int r = 0; r < 8; r++) { a0[r] = b2a; a1[r] = b2b; }
            mmacc<64, 32>(a0, a1, wq2i, h1buf + 16 * rh2, kq * 32);
            mmacc<64, 16>(a0, a1, wq2h, h2buf + 16 * rh2, kq * 16);
            stage8(gbuf + (8 * rh2) * GROW + kq * 256 + 4 * q2, a0, a1);
        }
        __syncthreads();   // S4: gbuf(L2) complete; h1buf/h2buf reads done

        // ---- layer2 elementwise: unit j2, rows r0q..r0q+1 (sum 4 partials) ----
        {
#pragma unroll
            for (int r = 0; r < 2; r++) {
                int row = r0q + r;
                const float* gr = gbuf + row * GROW;
                float gi = gr[j2]       + gr[256 + j2] + gr[512 + j2] + gr[768 + j2];
                float gf = gr[64 + j2]  + gr[320 + j2] + gr[576 + j2] + gr[832 + j2];
                float gg = gr[128 + j2] + gr[384 + j2] + gr[640 + j2] + gr[896 + j2];
                float go = gr[192 + j2] + gr[448 + j2] + gr[704 + j2] + gr[960 + j2];
                float iv = sigm(gi);
                float fv = sigm(gf);
                float gv = tanh_(gg);
                float ov = sigm(go);
                c2s[r] = fv * c2s[r] + iv * gv;
                float hv = ov * tanh_(c2s[r]);
                *(float2*)&h2buf[j2 * ST2 + 2 * row] = make_float2(hv, hv);
            }
        }
        // no barrier: next-step S1 orders gbuf/h2buf reads vs subsequent writes
    }

    __syncthreads();   // h2buf final values visible to all threads

    // ---- dense + relu on final h2 (duplicated rows: row r at offset 2r) ----
    {
        int o  = t & 63;
        int r0 = (t >> 6) * 2;           // 2 rows per thread
        float bd = b_dense[o];
        float a0 = bd, a1 = bd;
        const float* wd = w_dense + o * 64;
#pragma unroll 8
        for (int k = 0; k < 64; k++) {
            float wv = wd[k];
            const float* h = &h2buf[k * ST2 + 2 * r0];
            a0 += wv * h[0];
            a1 += wv * h[2];
        }
        out[(b0 + r0 + 0) * OUTD + o] = fmaxf(a0, 0.0f);
        out[(b0 + r0 + 1) * OUTD + o] = fmaxf(a1, 0.0f);
    }
}

#define SMEM_BYTES (((128 + 128 + 64) * ST2 + 16 * GROW) * 4)

extern "C" void kernel_launch(void* const* d_in, const int* in_sizes, int n_in,
                              void* d_out, int out_size) {
    const float* x       = (const float*)d_in[0];
    const float* w_ih1   = (const float*)d_in[1];
    const float* w_hh1   = (const float*)d_in[2];
    const float* b_ih1   = (const float*)d_in[3];
    const float* b_hh1   = (const float*)d_in[4];
    const float* w_ih2   = (const float*)d_in[5];
    const float* w_hh2   = (const float*)d_in[6];
    const float* b_ih2   = (const float*)d_in[7];
    const float* b_hh2   = (const float*)d_in[8];
    const float* w_dense = (const float*)d_in[9];
    const float* b_dense = (const float*)d_in[10];
    float* out = (float*)d_out;

    static int attr_set = 0;
    if (!attr_set) {
        cudaFuncSetAttribute(lstm_main, cudaFuncAttributeMaxDynamicSharedMemorySize, SMEM_BYTES);
        attr_set = 1;
    }

    transpose_kernel<<<704, 256>>>(w_ih1, w_hh1, w_ih2, w_hh2);
    lstm_main<<<B_TOT / NB, NTH, SMEM_BYTES>>>(x, b_ih1, b_hh1, b_ih2, b_hh2,
                                               w_dense, b_dense, out);
}